// round 5
// baseline (speedup 1.0000x reference)
#include <cuda_runtime.h>
#include <math.h>

// CurveGraphic2d: B=16 cubic Bezier curves rendered onto 16 x 256x256 canvases.
// Reference: sample 32 points along (possibly arc-length-truncated) curve,
// per-pixel min distance to samples, canvas = clip(1 - (d/w + eps)^aa, 0, 1).

#define CANVAS_H 256
#define CANVAS_W 256
#define NSAMP 32
#define MAX_LEN 300.0f
#define EPS 1e-6f

__global__ __launch_bounds__(256)
void curve_graphic_kernel(const float* __restrict__ inputs,   // [16,4,2]
                          const float* __restrict__ widths,   // [16]
                          const float* __restrict__ aafac,    // [16]
                          float* __restrict__ out)            // [16,256,256]
{
    // Samples stored as interleaved (y,x) pairs; float4 = 2 samples per load.
    __shared__ float4 ssamp[NSAMP / 2];

    const int b   = blockIdx.y;   // curve index
    const int y   = blockIdx.x;   // canvas row
    const int tid = threadIdx.x;  // canvas column

    // ---- Prelude: warp 0 computes the 32 sample points for curve b ----
    if (tid < 32) {
        const int s = tid;
        // Control points scaled to canvas: component 0 -> *H (y), component 1 -> *W (x)
        float cy[4], cx[4];
#pragma unroll
        for (int i = 0; i < 4; i++) {
            cy[i] = inputs[(b * 4 + i) * 2 + 0] * (float)CANVAS_H;
            cx[i] = inputs[(b * 4 + i) * 2 + 1] * (float)CANVAS_W;
        }

        const float t = (float)s / 31.0f;   // linspace(0,1,32)
        const float u = 1.0f - t;
        // Cubic Bernstein basis
        const float B0 = u * u * u;
        const float B1 = 3.0f * t * u * u;
        const float B2 = 3.0f * t * t * u;
        const float B3 = t * t * t;

        // Full-curve sample (for arc length)
        const float py = B0 * cy[0] + B1 * cy[1] + B2 * cy[2] + B3 * cy[3];
        const float px = B0 * cx[0] + B1 * cx[1] + B2 * cx[2] + B3 * cx[3];

        // Piecewise-linear arc length via warp shuffle
        const float pym = __shfl_up_sync(0xffffffffu, py, 1);
        const float pxm = __shfl_up_sync(0xffffffffu, px, 1);
        const float dyy = py - pym;
        const float dxx = px - pxm;
        float seg = (s > 0) ? sqrtf(dyy * dyy + dxx * dxx) : 0.0f;
#pragma unroll
        for (int off = 16; off; off >>= 1)
            seg += __shfl_xor_sync(0xffffffffu, seg, off);
        const float arc = seg;  // identical on all lanes

        // Truncation parameter
        const float tt = fminf(1.0f, MAX_LEN / (arc + EPS));
        const float ut = 1.0f - tt;

        // de Casteljau left subdivision at tt: left CPs = [a0, b0, c0, d0]
        const float b0y = ut * cy[0] + tt * cy[1], b0x = ut * cx[0] + tt * cx[1];
        const float b1y = ut * cy[1] + tt * cy[2], b1x = ut * cx[1] + tt * cx[2];
        const float b2y = ut * cy[2] + tt * cy[3], b2x = ut * cx[2] + tt * cx[3];
        const float c0y = ut * b0y + tt * b1y,     c0x = ut * b0x + tt * b1x;
        const float c1y = ut * b1y + tt * b2y,     c1x = ut * b1x + tt * b2x;
        const float d0y = ut * c0y + tt * c1y,     d0x = ut * c0x + tt * c1x;

        // Re-evaluate truncated curve at the same ts (same Bernstein basis)
        const float sy = B0 * cy[0] + B1 * b0y + B2 * c0y + B3 * d0y;
        const float sx = B0 * cx[0] + B1 * b0x + B2 * c0x + B3 * d0x;

        ((float2*)ssamp)[s] = make_float2(sy, sx);
    }
    __syncthreads();

    // ---- Main loop: min squared distance to 32 samples ----
    const float fy = (float)y;
    const float fx = (float)tid;
    float m = 3.4e38f;
#pragma unroll
    for (int k = 0; k < NSAMP / 2; k++) {
        const float4 v = ssamp[k];   // (y0, x0, y1, x1) — broadcast LDS.128
        const float dy0 = fy - v.x;
        const float dx0 = fx - v.y;
        m = fminf(m, fmaf(dy0, dy0, dx0 * dx0));
        const float dy1 = fy - v.z;
        const float dx1 = fx - v.w;
        m = fminf(m, fmaf(dy1, dy1, dx1 * dx1));
    }

    const float md   = sqrtf(m);
    const float base = md / widths[b] + EPS;
    const float val  = 1.0f - __powf(base, aafac[b]);
    out[(b * CANVAS_H + y) * CANVAS_W + tid] = fminf(fmaxf(val, 0.0f), 1.0f);
}

extern "C" void kernel_launch(void* const* d_in, const int* in_sizes, int n_in,
                              void* d_out, int out_size)
{
    const float* inputs = (const float*)d_in[0];   // [16,4,2]
    const float* widths = (const float*)d_in[1];   // [16]
    const float* aafac  = (const float*)d_in[2];   // [16]
    float* out = (float*)d_out;                    // [16,256,256]

    dim3 grid(CANVAS_H, 16);   // one block per (row, curve)
    curve_graphic_kernel<<<grid, CANVAS_W>>>(inputs, widths, aafac, out);
}

// round 6
// speedup vs baseline: 1.3343x; 1.3343x over previous
#include <cuda_runtime.h>
#include <math.h>

// CurveGraphic2d: 16 cubic Beziers -> 16 x 256x256 canvases.
// canvas = clip(1 - (min_d/w + eps)^aa, 0, 1); w <= 8 so any pixel with
// min_d >= w is exactly 0 -> aggressive tile/warp culling is exact.

#define CANVAS_H 256
#define CANVAS_W 256
#define NSAMP 32
#define MAX_LEN 300.0f
#define EPS 1e-6f

__global__ __launch_bounds__(256)
void curve_graphic_kernel(const float* __restrict__ inputs,   // [16,4,2]
                          const float* __restrict__ widths,   // [16]
                          const float* __restrict__ aafac,    // [16]
                          float* __restrict__ out)            // [16,256,256]
{
    // 32 samples as interleaved (y,x); float4 = 2 samples per LDS.128.
    __shared__ float4 ssamp[NSAMP / 2];
    __shared__ int s_skip;

    const int b    = blockIdx.y;          // curve / canvas index
    const int tile = blockIdx.x;          // 0..255 : 16x16 grid of 16x16 tiles
    const int ty0  = (tile >> 4) << 4;    // tile origin row
    const int tx0  = (tile & 15) << 4;    // tile origin col
    const int tid  = threadIdx.x;

    const float w = widths[b];

    // ---- Prelude: warp 0 computes the 32 sample points + tile cull ----
    if (tid < 32) {
        const int s = tid;
        float cy[4], cx[4];
#pragma unroll
        for (int i = 0; i < 4; i++) {
            cy[i] = inputs[(b * 4 + i) * 2 + 0] * (float)CANVAS_H;
            cx[i] = inputs[(b * 4 + i) * 2 + 1] * (float)CANVAS_W;
        }

        const float t = (float)s / 31.0f;           // linspace(0,1,32)
        const float u = 1.0f - t;
        const float B0 = u * u * u;
        const float B1 = 3.0f * t * u * u;
        const float B2 = 3.0f * t * t * u;
        const float B3 = t * t * t;

        // Full-curve sample (arc length)
        const float py = B0 * cy[0] + B1 * cy[1] + B2 * cy[2] + B3 * cy[3];
        const float px = B0 * cx[0] + B1 * cx[1] + B2 * cx[2] + B3 * cx[3];

        const float pym = __shfl_up_sync(0xffffffffu, py, 1);
        const float pxm = __shfl_up_sync(0xffffffffu, px, 1);
        const float dyy = py - pym;
        const float dxx = px - pxm;
        float seg = (s > 0) ? sqrtf(dyy * dyy + dxx * dxx) : 0.0f;
#pragma unroll
        for (int off = 16; off; off >>= 1)
            seg += __shfl_xor_sync(0xffffffffu, seg, off);
        const float arc = seg;

        const float tt = fminf(1.0f, MAX_LEN / (arc + EPS));
        const float ut = 1.0f - tt;

        // de Casteljau left subdivision at tt
        const float b0y = ut * cy[0] + tt * cy[1], b0x = ut * cx[0] + tt * cx[1];
        const float b1y = ut * cy[1] + tt * cy[2], b1x = ut * cx[1] + tt * cx[2];
        const float b2y = ut * cy[2] + tt * cy[3], b2x = ut * cx[2] + tt * cx[3];
        const float c0y = ut * b0y + tt * b1y,     c0x = ut * b0x + tt * b1x;
        const float c1y = ut * b1y + tt * b2y,     c1x = ut * b1x + tt * b2x;
        const float d0y = ut * c0y + tt * c1y,     d0x = ut * c0x + tt * c1x;

        // Truncated-curve sample
        const float sy = B0 * cy[0] + B1 * b0y + B2 * c0y + B3 * d0y;
        const float sx = B0 * cx[0] + B1 * b0x + B2 * c0x + B3 * d0x;

        ((float2*)ssamp)[s] = make_float2(sy, sx);

        // Tile cull: min squared distance from tile center to samples.
        // Tile half-diagonal r = 8*sqrt(2) = 11.3137; +1 px safety margin.
        const float cdy = (float)ty0 + 7.5f - sy;
        const float cdx = (float)tx0 + 7.5f - sx;
        float d2 = cdy * cdy + cdx * cdx;
#pragma unroll
        for (int off = 16; off; off >>= 1)
            d2 = fminf(d2, __shfl_xor_sync(0xffffffffu, d2, off));
        if (s == 0) {
            const float thr = w + 11.3137085f + 1.0f;
            s_skip = (d2 >= thr * thr) ? 1 : 0;
        }
    }
    __syncthreads();

    const int lx = tid & 15;              // col within tile
    const int ly = tid >> 4;              // row within tile
    const int py = ty0 + ly;
    const int px = tx0 + lx;
    float* const optr = out + (((b << 8) + py) << 8) + px;

    if (s_skip) { *optr = 0.0f; return; }

    // ---- Warp cull: each warp covers a 2x16 strip (rows ly&~1 .. +1) ----
    {
        const int lane = tid & 31;
        const float2 sp = ((const float2*)ssamp)[lane];
        const float wcy = (float)(ty0 + (ly & ~1)) + 0.5f;
        const float wcx = (float)tx0 + 7.5f;
        const float ddy = wcy - sp.x;
        const float ddx = wcx - sp.y;
        float d2 = ddy * ddy + ddx * ddx;
#pragma unroll
        for (int off = 16; off; off >>= 1)
            d2 = fminf(d2, __shfl_xor_sync(0xffffffffu, d2, off));
        // strip half-diagonal = sqrt(7.5^2 + 0.5^2) = 7.5166; +0.5 margin
        const float thr = w + 7.517f + 0.5f;
        if (d2 >= thr * thr) { *optr = 0.0f; return; }   // warp-uniform
    }

    // ---- Full evaluation: min squared distance over 32 samples ----
    const float fy = (float)py;
    const float fx = (float)px;
    float m = 3.4e38f;
#pragma unroll
    for (int k = 0; k < NSAMP / 2; k++) {
        const float4 v = ssamp[k];        // broadcast LDS.128, two samples
        const float dy0 = fy - v.x;
        const float dx0 = fx - v.y;
        m = fminf(m, fmaf(dy0, dy0, dx0 * dx0));
        const float dy1 = fy - v.z;
        const float dx1 = fx - v.w;
        m = fminf(m, fmaf(dy1, dy1, dx1 * dx1));
    }

    const float md   = sqrtf(m);
    const float base = md / w + EPS;
    const float val  = 1.0f - __powf(base, aafac[b]);
    *optr = fminf(fmaxf(val, 0.0f), 1.0f);
}

extern "C" void kernel_launch(void* const* d_in, const int* in_sizes, int n_in,
                              void* d_out, int out_size)
{
    const float* inputs = (const float*)d_in[0];   // [16,4,2]
    const float* widths = (const float*)d_in[1];   // [16]
    const float* aafac  = (const float*)d_in[2];   // [16]
    float* out = (float*)d_out;                    // [16,256,256]

    dim3 grid(256, 16);       // 16x16 tiles per canvas, 16 canvases
    curve_graphic_kernel<<<grid, 256>>>(inputs, widths, aafac, out);
}